// round 1
// baseline (speedup 1.0000x reference)
#include <cuda_runtime.h>

#define N_ 128
#define C_ 64
#define T_ 128
#define V_ 25
#define R_ 8
#define O_ 64
#define P_ (T_*V_)          // 3200 pixels per (n, channel-plane)
#define ALPHA_ 1.0f

// Scratch (alloc-free: __device__ globals)
__device__ float g_xm[N_*C_*V_];          // (N,C,V)       0.8 MB
__device__ float g_top[N_*O_*V_*V_];      // (N,O,U,V)    20.5 MB
__device__ float g_x3[(size_t)N_*O_*T_*V_]; // (N,O,T,V) 104.9 MB

// ---------------------------------------------------------------------------
// K1: xm[n,c,v] = mean_t x[n,c,t,v].  One block per (n,c) row-plane.
// warp w sums t = w, w+8, ...; lane = v. Cross-warp reduce in smem.
// ---------------------------------------------------------------------------
__global__ void k_mean(const float* __restrict__ x) {
    int nc   = blockIdx.x;              // n*C_ + c
    int w    = threadIdx.x >> 5;
    int lane = threadIdx.x & 31;
    const float* base = x + (size_t)nc * (T_*V_);
    float acc = 0.f;
    if (lane < V_) {
        for (int t = w; t < T_; t += 8)
            acc += base[t*V_ + lane];
    }
    __shared__ float s[8][V_];
    if (lane < V_) s[w][lane] = acc;
    __syncthreads();
    if (w == 0 && lane < V_) {
        float r = 0.f;
        #pragma unroll
        for (int i = 0; i < 8; i++) r += s[i][lane];
        g_xm[nc*V_ + lane] = r * (1.0f / T_);
    }
}

// ---------------------------------------------------------------------------
// K2: per n: x1 = w1@xm+b1, x2 = w2@xm+b2, d = tanh(x1[u]-x2[v]),
//            top[o,u,v] = (sum_r w4[o,r] d[r,u,v] + b4[o])*ALPHA + A[u,v]
// One block per n, 256 threads. Everything tiny -> smem resident.
// ---------------------------------------------------------------------------
__global__ void k_top(const float* __restrict__ A,
                      const float* __restrict__ w1, const float* __restrict__ b1,
                      const float* __restrict__ w2, const float* __restrict__ b2,
                      const float* __restrict__ w4, const float* __restrict__ b4) {
    int n = blockIdx.x;
    __shared__ float xm_s[C_*V_];          // 1600
    __shared__ float w1_s[R_*C_], w2_s[R_*C_];
    __shared__ float w4_s[O_*R_];
    __shared__ float A_s[V_*V_];
    __shared__ float x1_s[R_*V_], x2_s[R_*V_];
    __shared__ float d_s[R_*V_*V_];        // 5000
    __shared__ float b1_s[R_], b2_s[R_], b4_s[O_];
    int tid = threadIdx.x;

    for (int i = tid; i < C_*V_; i += 256) xm_s[i] = g_xm[n*C_*V_ + i];
    for (int i = tid; i < R_*C_; i += 256) { w1_s[i] = w1[i]; w2_s[i] = w2[i]; }
    for (int i = tid; i < O_*R_; i += 256) w4_s[i] = w4[i];
    for (int i = tid; i < V_*V_; i += 256) A_s[i] = A[i];
    if (tid < R_) { b1_s[tid] = b1[tid]; b2_s[tid] = b2[tid]; }
    if (tid < O_) b4_s[tid] = b4[tid];
    __syncthreads();

    for (int i = tid; i < 2*R_*V_; i += 256) {
        int which = i / (R_*V_);
        int j = i % (R_*V_);
        int r = j / V_, v = j % V_;
        const float* w = which ? w2_s : w1_s;
        float s = which ? b2_s[r] : b1_s[r];
        #pragma unroll 16
        for (int c = 0; c < C_; c++) s += w[r*C_ + c] * xm_s[c*V_ + v];
        (which ? x2_s : x1_s)[j] = s;
    }
    __syncthreads();

    for (int i = tid; i < R_*V_*V_; i += 256) {
        int r  = i / (V_*V_);
        int uv = i % (V_*V_);
        int u = uv / V_, v = uv % V_;
        d_s[i] = tanhf(x1_s[r*V_ + u] - x2_s[r*V_ + v]);
    }
    __syncthreads();

    float* topn = g_top + (size_t)n * (O_*V_*V_);
    for (int i = tid; i < O_*V_*V_; i += 256) {
        int o  = i / (V_*V_);
        int uv = i % (V_*V_);
        float s = b4_s[o];
        #pragma unroll
        for (int r = 0; r < R_; r++) s += w4_s[o*R_ + r] * d_s[r*V_*V_ + uv];
        topn[i] = s * ALPHA_ + A_s[uv];
    }
}

// ---------------------------------------------------------------------------
// K3: x3[n,o,p] = sum_c w3[o,c] * x[n,c,p] + b3[o]   (p = t*V+v, 3200 per n)
// Block: one n, 256-pixel tile, all 64 o. Thread: 8o x 8p register tile.
// smem: w3 transposed [c][o] (float4-loadable over o) + 16x256 x chunk.
// ---------------------------------------------------------------------------
__global__ void k_x3(const float* __restrict__ x, const float* __restrict__ w3,
                     const float* __restrict__ b3) {
    int n  = blockIdx.y;
    int P0 = blockIdx.x * 256;
    __shared__ float w3t[C_*O_];     // [c*64 + o]  16 KB
    __shared__ float b3_s[O_];
    __shared__ float xs[16*256];     // 16 KB
    int tid = threadIdx.x;

    for (int i = tid; i < C_*O_; i += 256) {
        int c = i >> 6, o = i & 63;
        w3t[i] = w3[o*C_ + c];
    }
    if (tid < O_) b3_s[tid] = b3[tid];

    const float* xn = x + (size_t)n * C_ * P_;
    int oo = (tid >> 5) * 8;         // 0..56
    int pp = (tid & 31) * 8;         // 0..248
    float acc[8][8];
    #pragma unroll
    for (int i = 0; i < 8; i++)
        #pragma unroll
        for (int j = 0; j < 8; j++) acc[i][j] = 0.f;

    for (int cc = 0; cc < C_; cc += 16) {
        __syncthreads();
        for (int i = tid*4; i < 16*256; i += 256*4) {
            int row = i >> 8;
            int col = i & 255;
            int p = P0 + col;
            float4 val = make_float4(0.f, 0.f, 0.f, 0.f);
            if (p < P_) val = *(const float4*)(xn + (size_t)(cc+row)*P_ + p);
            *(float4*)(xs + i) = val;
        }
        __syncthreads();
        #pragma unroll
        for (int c = 0; c < 16; c++) {
            float4 wa = *(float4*)&w3t[(cc+c)*O_ + oo];
            float4 wb = *(float4*)&w3t[(cc+c)*O_ + oo + 4];
            float4 xa = *(float4*)&xs[c*256 + pp];
            float4 xb = *(float4*)&xs[c*256 + pp + 4];
            float wr[8] = {wa.x,wa.y,wa.z,wa.w, wb.x,wb.y,wb.z,wb.w};
            float xr[8] = {xa.x,xa.y,xa.z,xa.w, xb.x,xb.y,xb.z,xb.w};
            #pragma unroll
            for (int i = 0; i < 8; i++)
                #pragma unroll
                for (int j = 0; j < 8; j++) acc[i][j] += wr[i]*xr[j];
        }
    }

    float* x3n = g_x3 + (size_t)n * O_ * P_;
    #pragma unroll
    for (int i = 0; i < 8; i++) {
        int o = oo + i;
        float b = b3_s[o];
        #pragma unroll
        for (int j = 0; j < 8; j += 4) {
            int p = P0 + pp + j;
            if (p < P_) {
                float4 v = make_float4(acc[i][j]+b, acc[i][j+1]+b,
                                       acc[i][j+2]+b, acc[i][j+3]+b);
                *(float4*)(x3n + (size_t)o*P_ + p) = v;
            }
        }
    }
}

// ---------------------------------------------------------------------------
// K4: out[n,o,t,u] = sum_v top[n,o,u,v] * x3[n,o,t,v]
// Batched (128x25)@(25x25)^T. Block = 2 (n,o) pairs x 80 threads.
// Thread: 5u x 8t register tile (t interleaved stride 16 -> conflict-free LDS).
// Results staged back through smem for fully coalesced global stores.
// ---------------------------------------------------------------------------
__global__ void k_out(float* __restrict__ out) {
    int pair = threadIdx.x / 80;
    int s    = threadIdx.x % 80;
    int no   = blockIdx.x * 2 + pair;           // n*O_ + o

    __shared__ float x3_s[2][T_*V_];            // 2 x 12.8 KB
    __shared__ float top_s[2][V_*V_];           // 2 x 2.5 KB

    const float* x3p  = g_x3 + (size_t)no * P_;
    const float* topp = g_top + (size_t)no * (V_*V_);
    for (int i = s; i < P_;    i += 80) x3_s[pair][i]  = x3p[i];
    for (int i = s; i < V_*V_; i += 80) top_s[pair][i] = topp[i];
    __syncthreads();

    int tg = s % 16;       // t = tg + 16*j
    int ug = s / 16;       // u = ug + 5*i
    float acc[5][8];
    #pragma unroll
    for (int i = 0; i < 5; i++)
        #pragma unroll
        for (int j = 0; j < 8; j++) acc[i][j] = 0.f;

    #pragma unroll 5
    for (int v = 0; v < V_; v++) {
        float tr[5], xr[8];
        #pragma unroll
        for (int i = 0; i < 5; i++) tr[i] = top_s[pair][(ug + 5*i)*V_ + v];
        #pragma unroll
        for (int j = 0; j < 8; j++) xr[j] = x3_s[pair][(tg + 16*j)*V_ + v];
        #pragma unroll
        for (int i = 0; i < 5; i++)
            #pragma unroll
            for (int j = 0; j < 8; j++) acc[i][j] += tr[i]*xr[j];
    }
    __syncthreads();

    #pragma unroll
    for (int i = 0; i < 5; i++)
        #pragma unroll
        for (int j = 0; j < 8; j++)
            x3_s[pair][(tg + 16*j)*V_ + (ug + 5*i)] = acc[i][j];
    __syncthreads();

    float* outp = out + (size_t)no * P_;
    for (int i = s; i < P_; i += 80) outp[i] = x3_s[pair][i];
}

// ---------------------------------------------------------------------------
extern "C" void kernel_launch(void* const* d_in, const int* in_sizes, int n_in,
                              void* d_out, int out_size) {
    const float* x  = (const float*)d_in[0];
    const float* A  = (const float*)d_in[1];
    const float* w1 = (const float*)d_in[2];
    const float* b1 = (const float*)d_in[3];
    const float* w2 = (const float*)d_in[4];
    const float* b2 = (const float*)d_in[5];
    const float* w3 = (const float*)d_in[6];
    const float* b3 = (const float*)d_in[7];
    const float* w4 = (const float*)d_in[8];
    const float* b4 = (const float*)d_in[9];
    float* out = (float*)d_out;

    k_mean<<<N_*C_, 256>>>(x);
    k_top<<<N_, 256>>>(A, w1, b1, w2, b2, w4, b4);
    k_x3<<<dim3((P_ + 255)/256, N_), 256>>>(x, w3, b3);
    k_out<<<N_*O_/2, 160>>>(out);
}